// round 4
// baseline (speedup 1.0000x reference)
#include <cuda_runtime.h>
#include <cuda_bf16.h>
#include <cstdint>

#define MM 8192
#define DD 2048
#define NN 8192
#define TOPK 819

// ---------------- static scratch (no dynamic allocation allowed) ----------
__device__ double g_partial[4096];          // block partial sums (2 matrices)
__device__ float  g_scale[2];               // scale_syn, scale_out

__device__ __align__(16) uint2          g_X3[(size_t)MM * DD];      // x limbs (h1|h2<<16, h3) 128MB
__device__ __align__(16) unsigned short g_Q1[(size_t)NN * DD];      // ternary W_syn as bf16  32MB
__device__ __align__(16) unsigned short g_Q2[(size_t)DD * NN];      // ternary W_out as bf16  32MB
__device__ __align__(16) float          g_Z [(size_t)MM * NN];      // z                      256MB
__device__                float          g_TH[MM];                   // per-row kth largest
__device__ __align__(16) uint32_t       g_H2[(size_t)MM * NN];      // hidden limbs (h1|h2)   256MB
__device__ __align__(16) float          g_XO[(size_t)MM * DD];      // x + mlp_out            64MB

// ---------------- scale = mean(|W|), deterministic fp64 tree --------------
__global__ void k_abs_partial(const float* __restrict__ W, int which) {
    __shared__ double sd[256];
    size_t base = (size_t)blockIdx.x * 8192 + threadIdx.x;
    double s = 0.0;
#pragma unroll
    for (int i = 0; i < 32; i++) s += (double)fabsf(W[base + (size_t)i * 256]);
    sd[threadIdx.x] = s; __syncthreads();
    for (int o = 128; o > 0; o >>= 1) {
        if ((int)threadIdx.x < o) sd[threadIdx.x] += sd[threadIdx.x + o];
        __syncthreads();
    }
    if (threadIdx.x == 0) g_partial[which * 2048 + blockIdx.x] = sd[0];
}

__global__ void k_finalize_scales() {
    __shared__ double sd[256];
    for (int w = 0; w < 2; w++) {
        double s = 0.0;
        for (int i = threadIdx.x; i < 2048; i += 256) s += g_partial[w * 2048 + i];
        sd[threadIdx.x] = s; __syncthreads();
        for (int o = 128; o > 0; o >>= 1) {
            if ((int)threadIdx.x < o) sd[threadIdx.x] += sd[threadIdx.x + o];
            __syncthreads();
        }
        if (threadIdx.x == 0) g_scale[w] = (float)(sd[0] / 16777216.0);
        __syncthreads();
    }
}

// ---------------- ternary quantization (store {-1,0,+1} as bf16) ----------
__device__ __forceinline__ unsigned short tq1(float w, float den) {
    float t = __fdiv_rn(w, den);          // IEEE division (match reference)
    float q = fmaxf(-1.0f, fminf(1.0f, rintf(t)));   // round half-to-even
    return __bfloat16_as_ushort(__float2bfloat16_rn(q));  // exact: -1/0/+1
}

__global__ void k_quant(const float4* __restrict__ W, int which) {
    size_t i = (size_t)blockIdx.x * blockDim.x + threadIdx.x;   // one float4 each
    float den = g_scale[which] + 1e-8f;
    float4 w = W[i];
    ushort4 q;
    q.x = tq1(w.x, den); q.y = tq1(w.y, den); q.z = tq1(w.z, den); q.w = tq1(w.w, den);
    ushort4* Q = reinterpret_cast<ushort4*>(which ? g_Q2 : g_Q1);
    Q[i] = q;
}

// ---------------- x -> 3 bf16 limbs (exact fp32 decomposition) ------------
__global__ void k_xlimbs(const float4* __restrict__ x) {
    size_t i = (size_t)blockIdx.x * blockDim.x + threadIdx.x;   // one float4 each
    float4 v = x[i];
    uint2 o[4];
    float f[4] = {v.x, v.y, v.z, v.w};
#pragma unroll
    for (int j = 0; j < 4; j++) {
        __nv_bfloat16 b1 = __float2bfloat16_rn(f[j]);
        float r1 = f[j] - __bfloat162float(b1);
        __nv_bfloat16 b2 = __float2bfloat16_rn(r1);
        float r2 = r1 - __bfloat162float(b2);
        __nv_bfloat16 b3 = __float2bfloat16_rn(r2);
        o[j].x = (uint32_t)__bfloat16_as_ushort(b1) | ((uint32_t)__bfloat16_as_ushort(b2) << 16);
        o[j].y = (uint32_t)__bfloat16_as_ushort(b3);
    }
    uint4* dst = reinterpret_cast<uint4*>(g_X3);
    dst[2 * i]     = make_uint4(o[0].x, o[0].y, o[1].x, o[1].y);
    dst[2 * i + 1] = make_uint4(o[2].x, o[2].y, o[3].x, o[3].y);
}

// ---------------- mma.sync m16n8k16 bf16 -----------------------------------
__device__ __forceinline__ void mma16816(float* c, uint32_t a0, uint32_t a1,
                                         uint32_t a2, uint32_t a3,
                                         uint32_t b0, uint32_t b1) {
    asm volatile(
        "mma.sync.aligned.m16n8k16.row.col.f32.bf16.bf16.f32 "
        "{%0,%1,%2,%3}, {%4,%5,%6,%7}, {%8,%9}, {%0,%1,%2,%3};\n"
        : "+f"(c[0]), "+f"(c[1]), "+f"(c[2]), "+f"(c[3])
        : "r"(a0), "r"(a1), "r"(a2), "r"(a3), "r"(b0), "r"(b1));
}

// ---------------- GEMM1: z = scale1 * (sum_limbs x_l @ T1^T) + b_syn ------
// CTA 128x128, warps 2(m) x 4(n), warp tile 64x32, 3 limbs.
__global__ void __launch_bounds__(256) k_gemm1(const float* __restrict__ b_syn) {
    const int warp = threadIdx.x >> 5, lane = threadIdx.x & 31;
    const int wm = warp >> 2, wn = warp & 3;
    const int tr = lane >> 2, tc = lane & 3;
    const int m0 = blockIdx.y * 128 + wm * 64;
    const int n0 = blockIdx.x * 128 + wn * 32;

    float acc[4][4][4];
#pragma unroll
    for (int a = 0; a < 4; a++)
#pragma unroll
        for (int b = 0; b < 4; b++)
#pragma unroll
            for (int c = 0; c < 4; c++) acc[a][b][c] = 0.0f;

    const uint4*    Xp = reinterpret_cast<const uint4*>(g_X3);     // 1 uint4 = 2 elems
    const uint32_t* Bp = reinterpret_cast<const uint32_t*>(g_Q1);  // 1 uint  = 2 bf16

    for (int kk = 0; kk < DD; kk += 16) {
        uint32_t bf[4][2];
#pragma unroll
        for (int nt = 0; nt < 4; nt++) {
            size_t bi = ((size_t)(n0 + nt * 8 + tr) * DD + kk + tc * 2) >> 1;
            bf[nt][0] = Bp[bi];
            bf[nt][1] = Bp[bi + 4];
        }
#pragma unroll
        for (int mt = 0; mt < 4; mt++) {
            size_t ai = ((size_t)(m0 + mt * 16 + tr) * DD + kk + tc * 2) >> 1;
            uint4 v00 = Xp[ai];
            uint4 v10 = Xp[ai + 4 * DD];        // +8 rows
            uint4 v01 = Xp[ai + 4];             // +8 cols
            uint4 v11 = Xp[ai + 4 * DD + 4];
#pragma unroll
            for (int l = 0; l < 3; l++) {
                uint32_t a0, a1, a2, a3;
                if (l == 0) {
                    a0 = __byte_perm(v00.x, v00.z, 0x5410); a1 = __byte_perm(v10.x, v10.z, 0x5410);
                    a2 = __byte_perm(v01.x, v01.z, 0x5410); a3 = __byte_perm(v11.x, v11.z, 0x5410);
                } else if (l == 1) {
                    a0 = __byte_perm(v00.x, v00.z, 0x7632); a1 = __byte_perm(v10.x, v10.z, 0x7632);
                    a2 = __byte_perm(v01.x, v01.z, 0x7632); a3 = __byte_perm(v11.x, v11.z, 0x7632);
                } else {
                    a0 = __byte_perm(v00.y, v00.w, 0x5410); a1 = __byte_perm(v10.y, v10.w, 0x5410);
                    a2 = __byte_perm(v01.y, v01.w, 0x5410); a3 = __byte_perm(v11.y, v11.w, 0x5410);
                }
#pragma unroll
                for (int nt = 0; nt < 4; nt++)
                    mma16816(acc[mt][nt], a0, a1, a2, a3, bf[nt][0], bf[nt][1]);
            }
        }
    }

    const float s1 = g_scale[0];
#pragma unroll
    for (int mt = 0; mt < 4; mt++) {
        int r = m0 + mt * 16 + tr;
#pragma unroll
        for (int nt = 0; nt < 4; nt++) {
            int n = n0 + nt * 8 + tc * 2;
            float2 bs = *reinterpret_cast<const float2*>(b_syn + n);
            float2 o0 = make_float2(fmaf(acc[mt][nt][0], s1, bs.x),
                                    fmaf(acc[mt][nt][1], s1, bs.y));
            float2 o1 = make_float2(fmaf(acc[mt][nt][2], s1, bs.x),
                                    fmaf(acc[mt][nt][3], s1, bs.y));
            *reinterpret_cast<float2*>(g_Z + (size_t)r * NN + n)       = o0;
            *reinterpret_cast<float2*>(g_Z + (size_t)(r + 8) * NN + n) = o1;
        }
    }
}

// ---------------- exact per-row kth-largest (4-pass MSB radix select) -----
__device__ __forceinline__ uint32_t fmap(float f) {
    uint32_t b = __float_as_uint(f);
    return (b & 0x80000000u) ? ~b : (b | 0x80000000u);
}

__global__ void k_topk() {
    __shared__ uint32_t srow[NN];      // 32KB
    __shared__ uint32_t hist[256];
    __shared__ uint32_t s_prefix, s_kk;
    const int row = blockIdx.x;
    const uint4* zp = reinterpret_cast<const uint4*>(g_Z + (size_t)row * NN);
    for (int i = threadIdx.x; i < NN / 4; i += 256) {
        uint4 v = zp[i];
        srow[i * 4 + 0] = fmap(__uint_as_float(v.x));
        srow[i * 4 + 1] = fmap(__uint_as_float(v.y));
        srow[i * 4 + 2] = fmap(__uint_as_float(v.z));
        srow[i * 4 + 3] = fmap(__uint_as_float(v.w));
    }
    if (threadIdx.x == 0) { s_prefix = 0u; s_kk = TOPK; }
    __syncthreads();

    uint32_t maskhi = 0u;
    for (int b = 3; b >= 0; b--) {
        hist[threadIdx.x] = 0u;
        __syncthreads();
        const uint32_t pref = s_prefix;
        const int sh = 8 * b;
        for (int i = threadIdx.x; i < NN; i += 256) {
            uint32_t u = srow[i];
            if ((u & maskhi) == pref) atomicAdd(&hist[(u >> sh) & 0xFF], 1u);
        }
        __syncthreads();
        if (threadIdx.x == 0) {
            uint32_t cum = 0, kk = s_kk; int sel = 0;
            for (int v = 255; v >= 0; v--) {
                uint32_t c = hist[v];
                if (cum + c >= kk) { sel = v; s_kk = kk - cum; break; }
                cum += c;
            }
            s_prefix = pref | ((uint32_t)sel << sh);
        }
        __syncthreads();
        maskhi |= (0xFFu << (8 * b));
    }
    if (threadIdx.x == 0) {
        uint32_t u = s_prefix;
        uint32_t bits = (u & 0x80000000u) ? (u ^ 0x80000000u) : ~u;
        g_TH[row] = __uint_as_float(bits);
    }
}

// ---------------- hidden = where(z>=th, relu(z), 0) -> 2 bf16 limbs -------
__device__ __forceinline__ uint32_t packh(float z, float th) {
    float h = (z >= th && z > 0.0f) ? z : 0.0f;
    __nv_bfloat16 b1 = __float2bfloat16_rn(h);
    float r = h - __bfloat162float(b1);
    __nv_bfloat16 b2 = __float2bfloat16_rn(r);
    return (uint32_t)__bfloat16_as_ushort(b1) | ((uint32_t)__bfloat16_as_ushort(b2) << 16);
}

__global__ void k_hidden() {
    size_t i = ((size_t)blockIdx.x * 256 + threadIdx.x) * 4;
    float th = g_TH[i >> 13];   // / NN
    float4 z = *reinterpret_cast<const float4*>(g_Z + i);
    uint4 o;
    o.x = packh(z.x, th); o.y = packh(z.y, th);
    o.z = packh(z.z, th); o.w = packh(z.w, th);
    *reinterpret_cast<uint4*>(g_H2 + i) = o;
}

// ---------------- GEMM2: xo = x + scale2*(sum_limbs h_l @ T2^T) + b_out ---
__global__ void __launch_bounds__(256) k_gemm2(const float* __restrict__ b_out,
                                               const float* __restrict__ x) {
    const int warp = threadIdx.x >> 5, lane = threadIdx.x & 31;
    const int wm = warp >> 2, wn = warp & 3;
    const int tr = lane >> 2, tc = lane & 3;
    const int m0 = blockIdx.y * 128 + wm * 64;
    const int n0 = blockIdx.x * 128 + wn * 32;   // n == output dim d

    float acc[4][4][4];
#pragma unroll
    for (int a = 0; a < 4; a++)
#pragma unroll
        for (int b = 0; b < 4; b++)
#pragma unroll
            for (int c = 0; c < 4; c++) acc[a][b][c] = 0.0f;

    const uint2*    Ap = reinterpret_cast<const uint2*>(g_H2);     // 1 uint2 = 2 elems
    const uint32_t* Bp = reinterpret_cast<const uint32_t*>(g_Q2);

    for (int kk = 0; kk < NN; kk += 16) {
        uint32_t bf[4][2];
#pragma unroll
        for (int nt = 0; nt < 4; nt++) {
            size_t bi = ((size_t)(n0 + nt * 8 + tr) * NN + kk + tc * 2) >> 1;
            bf[nt][0] = Bp[bi];
            bf[nt][1] = Bp[bi + 4];
        }
#pragma unroll
        for (int mt = 0; mt < 4; mt++) {
            size_t ai = ((size_t)(m0 + mt * 16 + tr) * NN + kk + tc * 2) >> 1;
            uint2 v00 = Ap[ai];
            uint2 v10 = Ap[ai + 4 * NN];
            uint2 v01 = Ap[ai + 4];
            uint2 v11 = Ap[ai + 4 * NN + 4];
#pragma unroll
            for (int l = 0; l < 2; l++) {
                uint32_t sel = l ? 0x7632u : 0x5410u;
                uint32_t a0 = __byte_perm(v00.x, v00.y, sel);
                uint32_t a1 = __byte_perm(v10.x, v10.y, sel);
                uint32_t a2 = __byte_perm(v01.x, v01.y, sel);
                uint32_t a3 = __byte_perm(v11.x, v11.y, sel);
#pragma unroll
                for (int nt = 0; nt < 4; nt++)
                    mma16816(acc[mt][nt], a0, a1, a2, a3, bf[nt][0], bf[nt][1]);
            }
        }
    }

    const float s2 = g_scale[1];
#pragma unroll
    for (int mt = 0; mt < 4; mt++) {
        int r = m0 + mt * 16 + tr;
#pragma unroll
        for (int nt = 0; nt < 4; nt++) {
            int n = n0 + nt * 8 + tc * 2;
            float2 bo = *reinterpret_cast<const float2*>(b_out + n);
            float2 x0 = *reinterpret_cast<const float2*>(x + (size_t)r * DD + n);
            float2 x1 = *reinterpret_cast<const float2*>(x + (size_t)(r + 8) * DD + n);
            float2 o0 = make_float2(fmaf(acc[mt][nt][0], s2, bo.x) + x0.x,
                                    fmaf(acc[mt][nt][1], s2, bo.y) + x0.y);
            float2 o1 = make_float2(fmaf(acc[mt][nt][2], s2, bo.x) + x1.x,
                                    fmaf(acc[mt][nt][3], s2, bo.y) + x1.y);
            *reinterpret_cast<float2*>(g_XO + (size_t)r * DD + n)       = o0;
            *reinterpret_cast<float2*>(g_XO + (size_t)(r + 8) * DD + n) = o1;
        }
    }
}

// ---------------- layernorm over last dim ---------------------------------
__global__ void k_ln(const float* __restrict__ gamma, const float* __restrict__ beta,
                     float* __restrict__ out) {
    __shared__ float ssum[256], ssq[256];
    const int row = blockIdx.x, t = threadIdx.x;
    const float4* xp = reinterpret_cast<const float4*>(g_XO + (size_t)row * DD);
    float4 v0 = xp[t], v1 = xp[t + 256];
    float s = v0.x + v0.y + v0.z + v0.w + v1.x + v1.y + v1.z + v1.w;
    float q = v0.x * v0.x + v0.y * v0.y + v0.z * v0.z + v0.w * v0.w +
              v1.x * v1.x + v1.y * v1.y + v1.z * v1.z + v1.w * v1.w;
    ssum[t] = s; ssq[t] = q; __syncthreads();
    for (int o = 128; o > 0; o >>= 1) {
        if (t < o) { ssum[t] += ssum[t + o]; ssq[t] += ssq[t + o]; }
        __syncthreads();
    }
    float mu  = ssum[0] * (1.0f / DD);
    float var = ssq[0] * (1.0f / DD) - mu * mu;
    float rs  = rsqrtf(var + 1e-5f);
    const float4* gp = reinterpret_cast<const float4*>(gamma);
    const float4* bp = reinterpret_cast<const float4*>(beta);
    float4 g0 = gp[t], g1 = gp[t + 256];
    float4 b0 = bp[t], b1 = bp[t + 256];
    float4 o0, o1;
    o0.x = (v0.x - mu) * rs * g0.x + b0.x; o0.y = (v0.y - mu) * rs * g0.y + b0.y;
    o0.z = (v0.z - mu) * rs * g0.z + b0.z; o0.w = (v0.w - mu) * rs * g0.w + b0.w;
    o1.x = (v1.x - mu) * rs * g1.x + b1.x; o1.y = (v1.y - mu) * rs * g1.y + b1.y;
    o1.z = (v1.z - mu) * rs * g1.z + b1.z; o1.w = (v1.w - mu) * rs * g1.w + b1.w;
    float4* op = reinterpret_cast<float4*>(out + (size_t)row * DD);
    op[t] = o0; op[t + 256] = o1;
}

// ---------------- launcher -------------------------------------------------
extern "C" void kernel_launch(void* const* d_in, const int* in_sizes, int n_in,
                              void* d_out, int out_size) {
    (void)in_sizes; (void)n_in; (void)out_size;
    const float* x     = (const float*)d_in[0];
    const float* W_syn = (const float*)d_in[1];
    const float* b_syn = (const float*)d_in[2];
    const float* W_out = (const float*)d_in[3];
    const float* b_out = (const float*)d_in[4];
    const float* gamma = (const float*)d_in[5];
    const float* beta  = (const float*)d_in[6];
    float* out = (float*)d_out;

    k_abs_partial<<<2048, 256>>>(W_syn, 0);
    k_abs_partial<<<2048, 256>>>(W_out, 1);
    k_finalize_scales<<<1, 256>>>();
    k_quant<<<16384, 256>>>((const float4*)W_syn, 0);
    k_quant<<<16384, 256>>>((const float4*)W_out, 1);
    k_xlimbs<<<16384, 256>>>((const float4*)x);
    k_gemm1<<<dim3(64, 64), 256>>>(b_syn);
    k_topk<<<MM, 256>>>();
    k_hidden<<<65536, 256>>>();
    k_gemm2<<<dim3(16, 64), 256>>>(b_out, x);
    k_ln<<<MM, 256>>>(gamma, beta, out);
}

// round 7
// speedup vs baseline: 2.2386x; 2.2386x over previous
#include <cuda_runtime.h>
#include <cuda_bf16.h>
#include <cstdint>

#define MM 8192
#define DD 2048
#define NN 8192
#define TOPK 819
typedef unsigned short u16;

__device__ double g_partial[4096];
__device__ float  g_scale[2];
__device__ __align__(16) u16   g_X1[(size_t)MM * DD];
__device__ __align__(16) u16   g_X2[(size_t)MM * DD];
__device__ __align__(16) u16   g_X3[(size_t)MM * DD];
__device__ __align__(16) u16   g_Q1[(size_t)NN * DD];
__device__ __align__(16) u16   g_Q2[(size_t)DD * NN];
__device__ __align__(16) float g_Z [(size_t)MM * NN];
__device__                float g_TH[MM];
__device__ __align__(16) u16   g_H1[(size_t)MM * NN];
__device__ __align__(16) u16   g_H2[(size_t)MM * NN];
__device__ __align__(16) float g_XO[(size_t)MM * DD];

__device__ __forceinline__ uint32_t smem_u32(const void* p) {
    uint32_t a;
    asm("{ .reg .u64 t; cvta.to.shared.u64 t, %1; cvt.u32.u64 %0, t; }" : "=r"(a) : "l"(p));
    return a;
}
#define CP_COMMIT() asm volatile("cp.async.commit_group;" ::: "memory")
#define CP_WAIT(n)  asm volatile("cp.async.wait_group %0;" :: "n"(n) : "memory")

__device__ __forceinline__ void mma16816(float* c, uint32_t a0, uint32_t a1,
                                         uint32_t a2, uint32_t a3,
                                         uint32_t b0, uint32_t b1) {
    asm volatile(
        "mma.sync.aligned.m16n8k16.row.col.f32.bf16.bf16.f32 "
        "{%0,%1,%2,%3}, {%4,%5,%6,%7}, {%8,%9}, {%0,%1,%2,%3};\n"
        : "+f"(c[0]), "+f"(c[1]), "+f"(c[2]), "+f"(c[3])
        : "r"(a0), "r"(a1), "r"(a2), "r"(a3), "r"(b0), "r"(b1));
}

// ---------------- prep ------------------------------------------------------
__global__ void k_abs_partial(const float* __restrict__ W, int which) {
    __shared__ double sd[256];
    size_t base = (size_t)blockIdx.x * 8192 + threadIdx.x;
    double s = 0.0;
#pragma unroll
    for (int i = 0; i < 32; i++) s += (double)fabsf(W[base + (size_t)i * 256]);
    sd[threadIdx.x] = s; __syncthreads();
    for (int o = 128; o > 0; o >>= 1) {
        if ((int)threadIdx.x < o) sd[threadIdx.x] += sd[threadIdx.x + o];
        __syncthreads();
    }
    if (threadIdx.x == 0) g_partial[which * 2048 + blockIdx.x] = sd[0];
}
__global__ void k_finalize_scales() {
    __shared__ double sd[256];
    for (int w = 0; w < 2; w++) {
        double s = 0.0;
        for (int i = threadIdx.x; i < 2048; i += 256) s += g_partial[w * 2048 + i];
        sd[threadIdx.x] = s; __syncthreads();
        for (int o = 128; o > 0; o >>= 1) {
            if ((int)threadIdx.x < o) sd[threadIdx.x] += sd[threadIdx.x + o];
            __syncthreads();
        }
        if (threadIdx.x == 0) g_scale[w] = (float)(sd[0] / 16777216.0);
        __syncthreads();
    }
}
__device__ __forceinline__ u16 tq1(float w, float den) {
    float t = __fdiv_rn(w, den);
    float q = fmaxf(-1.0f, fminf(1.0f, rintf(t)));
    return __bfloat16_as_ushort(__float2bfloat16_rn(q));
}
__global__ void k_quant(const float4* __restrict__ W, int which) {
    size_t i = (size_t)blockIdx.x * blockDim.x + threadIdx.x;
    float den = g_scale[which] + 1e-8f;
    float4 w = W[i];
    ushort4 q;
    q.x = tq1(w.x, den); q.y = tq1(w.y, den); q.z = tq1(w.z, den); q.w = tq1(w.w, den);
    reinterpret_cast<ushort4*>(which ? g_Q2 : g_Q1)[i] = q;
}
__global__ void k_xlimbs3(const float4* __restrict__ x) {
    size_t i = (size_t)blockIdx.x * blockDim.x + threadIdx.x;
    float4 v = x[i];
    float f[4] = {v.x, v.y, v.z, v.w};
    ushort4 p1, p2, p3;
    u16* a1 = &p1.x; u16* a2 = &p2.x; u16* a3 = &p3.x;
#pragma unroll
    for (int j = 0; j < 4; j++) {
        __nv_bfloat16 b1 = __float2bfloat16_rn(f[j]);
        float r1 = f[j] - __bfloat162float(b1);
        __nv_bfloat16 b2 = __float2bfloat16_rn(r1);
        float r2 = r1 - __bfloat162float(b2);
        a1[j] = __bfloat16_as_ushort(b1);
        a2[j] = __bfloat16_as_ushort(b2);
        a3[j] = __bfloat16_as_ushort(__float2bfloat16_rn(r2));
    }
    reinterpret_cast<ushort4*>(g_X1)[i] = p1;
    reinterpret_cast<ushort4*>(g_X2)[i] = p2;
    reinterpret_cast<ushort4*>(g_X3)[i] = p3;
}

// ---------------- pipelined HMMA GEMM --------------------------------------
// CTA 128x128, 8 warps (2m x 4n), warp tile 64x32, k-step 32, 3-stage cp.async.
// smem tile: 128 rows x (64B data + 16B pad) = 10240B. Conflict-free LDS.
// GID selects global arrays INSIDE the kernel (device symbols must not cross
// the host boundary).
template<int GID, int NLIMB>
__global__ void __launch_bounds__(256) k_gemm_hmma(
    const float* __restrict__ bias, const float* __restrict__ xres) {
    constexpr int NT = NLIMB + 1;
    constexpr int TILE_U32  = 2560;           // 10240 B / 4
    constexpr int STAGE_U32 = NT * TILE_U32;
    constexpr int Kdim = (GID == 0) ? DD : NN;
    constexpr int Nout = (GID == 0) ? NN : DD;
    constexpr int steps = Kdim >> 5;

    extern __shared__ uint32_t sm[];
    const uint32_t smaddr = smem_u32(sm);
    const int tid = threadIdx.x;
    const int warp = tid >> 5, lane = tid & 31;
    const int wm = warp >> 2, wn = warp & 3;
    const int tr = lane >> 2, tc = lane & 3;
    const int m0 = blockIdx.y * 128, n0 = blockIdx.x * 128;

    const u16* gt[4]; int r0[4];
    if (GID == 0) {
        gt[0] = g_X1; gt[1] = g_X2; gt[2] = g_X3; gt[3] = g_Q1;
        r0[0] = m0; r0[1] = m0; r0[2] = m0; r0[3] = n0;
    } else {
        gt[0] = g_H1; gt[1] = g_H2; gt[2] = g_Q2; gt[3] = g_Q2;
        r0[0] = m0; r0[1] = m0; r0[2] = n0; r0[3] = n0;
    }
    float* Cout = (GID == 0) ? g_Z : g_XO;

    float acc[4][4][4];
#pragma unroll
    for (int a = 0; a < 4; a++)
#pragma unroll
        for (int b = 0; b < 4; b++)
#pragma unroll
            for (int c = 0; c < 4; c++) acc[a][b][c] = 0.0f;

    const int lrow = tid >> 2, lc16 = (tid & 3) * 16;
    const int lrow2 = (tid + 256) >> 2, lc162 = ((tid + 256) & 3) * 16;

    // prologue: stages 0,1
#pragma unroll
    for (int st = 0; st < 2; st++) {
#pragma unroll
        for (int tile = 0; tile < NT; tile++) {
            const char* gb = (const char*)(gt[tile] + (size_t)r0[tile] * Kdim + st * 32);
            uint32_t db = smaddr + (uint32_t)(st * STAGE_U32 + tile * TILE_U32) * 4;
            uint32_t d0 = db + lrow * 80 + lc16;
            const char* s0 = gb + (size_t)lrow * (Kdim * 2) + lc16;
            asm volatile("cp.async.cg.shared.global [%0], [%1], 16;" :: "r"(d0), "l"(s0) : "memory");
            uint32_t d1 = db + lrow2 * 80 + lc162;
            const char* s1 = gb + (size_t)lrow2 * (Kdim * 2) + lc162;
            asm volatile("cp.async.cg.shared.global [%0], [%1], 16;" :: "r"(d1), "l"(s1) : "memory");
        }
        CP_COMMIT();
    }

    for (int t = 0; t < steps; t++) {
        CP_WAIT(1);
        __syncthreads();
        if (t + 2 < steps) {
            int st = (t + 2) % 3, kk = (t + 2) * 32;
#pragma unroll
            for (int tile = 0; tile < NT; tile++) {
                const char* gb = (const char*)(gt[tile] + (size_t)r0[tile] * Kdim + kk);
                uint32_t db = smaddr + (uint32_t)(st * STAGE_U32 + tile * TILE_U32) * 4;
                uint32_t d0 = db + lrow * 80 + lc16;
                const char* s0 = gb + (size_t)lrow * (Kdim * 2) + lc16;
                asm volatile("cp.async.cg.shared.global [%0], [%1], 16;" :: "r"(d0), "l"(s0) : "memory");
                uint32_t d1 = db + lrow2 * 80 + lc162;
                const char* s1 = gb + (size_t)lrow2 * (Kdim * 2) + lc162;
                asm volatile("cp.async.cg.shared.global [%0], [%1], 16;" :: "r"(d1), "l"(s1) : "memory");
            }
        }
        CP_COMMIT();

        const uint32_t* s = sm + (t % 3) * STAGE_U32;
        const uint32_t* sB = s + NLIMB * TILE_U32;
#pragma unroll
        for (int half = 0; half < 2; half++) {
            const int co = half * 8 + tc;
            uint32_t bf[4][2];
#pragma unroll
            for (int nt = 0; nt < 4; nt++) {
                const uint32_t* bp = sB + (wn * 32 + nt * 8 + tr) * 20 + co;
                bf[nt][0] = bp[0]; bf[nt][1] = bp[4];
            }
#pragma unroll
            for (int mt = 0; mt < 4; mt++) {
                const int ar = (wm * 64 + mt * 16 + tr) * 20 + co;
#pragma unroll
                for (int l = 0; l < NLIMB; l++) {
                    const uint32_t* ap = s + l * TILE_U32 + ar;
                    uint32_t a0 = ap[0], a1 = ap[160], a2 = ap[4], a3 = ap[164];
#pragma unroll
                    for (int nt = 0; nt < 4; nt++)
                        mma16816(acc[mt][nt], a0, a1, a2, a3, bf[nt][0], bf[nt][1]);
                }
            }
        }
    }

    const float sc = g_scale[GID];
#pragma unroll
    for (int mt = 0; mt < 4; mt++) {
        int r = m0 + wm * 64 + mt * 16 + tr;
#pragma unroll
        for (int nt = 0; nt < 4; nt++) {
            int n = n0 + wn * 32 + nt * 8 + tc * 2;
            float2 bs = *reinterpret_cast<const float2*>(bias + n);
            float2 o0 = make_float2(fmaf(acc[mt][nt][0], sc, bs.x),
                                    fmaf(acc[mt][nt][1], sc, bs.y));
            float2 o1 = make_float2(fmaf(acc[mt][nt][2], sc, bs.x),
                                    fmaf(acc[mt][nt][3], sc, bs.y));
            if (GID == 1) {
                float2 x0 = *reinterpret_cast<const float2*>(xres + (size_t)r * Nout + n);
                float2 x1 = *reinterpret_cast<const float2*>(xres + (size_t)(r + 8) * Nout + n);
                o0.x += x0.x; o0.y += x0.y; o1.x += x1.x; o1.y += x1.y;
            }
            *reinterpret_cast<float2*>(Cout + (size_t)r * Nout + n)       = o0;
            *reinterpret_cast<float2*>(Cout + (size_t)(r + 8) * Nout + n) = o1;
        }
    }
}

// ---------------- exact per-row kth-largest (radix select) ----------------
__device__ __forceinline__ uint32_t fmap(float f) {
    uint32_t b = __float_as_uint(f);
    return (b & 0x80000000u) ? ~b : (b | 0x80000000u);
}
__global__ void k_topk() {
    __shared__ uint32_t srow[NN];
    __shared__ uint32_t hist[256];
    __shared__ uint32_t s_prefix, s_kk;
    const int row = blockIdx.x;
    const uint4* zp = reinterpret_cast<const uint4*>(g_Z + (size_t)row * NN);
    for (int i = threadIdx.x; i < NN / 4; i += 256) {
        uint4 v = zp[i];
        srow[i * 4 + 0] = fmap(__uint_as_float(v.x));
        srow[i * 4 + 1] = fmap(__uint_as_float(v.y));
        srow[i * 4 + 2] = fmap(__uint_as_float(v.z));
        srow[i * 4 + 3] = fmap(__uint_as_float(v.w));
    }
    if (threadIdx.x == 0) { s_prefix = 0u; s_kk = TOPK; }
    __syncthreads();
    uint32_t maskhi = 0u;
    for (int b = 3; b >= 0; b--) {
        hist[threadIdx.x] = 0u;
        __syncthreads();
        const uint32_t pref = s_prefix;
        const int sh = 8 * b;
        for (int i = threadIdx.x; i < NN; i += 256) {
            uint32_t u = srow[i];
            if ((u & maskhi) == pref) atomicAdd(&hist[(u >> sh) & 0xFF], 1u);
        }
        __syncthreads();
        if (threadIdx.x == 0) {
            uint32_t cum = 0, kk = s_kk; int sel = 0;
            for (int v = 255; v >= 0; v--) {
                uint32_t c = hist[v];
                if (cum + c >= kk) { sel = v; s_kk = kk - cum; break; }
                cum += c;
            }
            s_prefix = pref | ((uint32_t)sel << sh);
        }
        __syncthreads();
        maskhi |= (0xFFu << (8 * b));
    }
    if (threadIdx.x == 0) {
        uint32_t u = s_prefix;
        uint32_t bits = (u & 0x80000000u) ? (u ^ 0x80000000u) : ~u;
        g_TH[row] = __uint_as_float(bits);
    }
}

__global__ void k_hidden() {
    size_t i = ((size_t)blockIdx.x * 256 + threadIdx.x) * 4;
    float th = g_TH[i >> 13];
    float4 z = *reinterpret_cast<const float4*>(g_Z + i);
    float f[4] = {z.x, z.y, z.z, z.w};
    ushort4 p1, p2;
    u16* a1 = &p1.x; u16* a2 = &p2.x;
#pragma unroll
    for (int j = 0; j < 4; j++) {
        float h = (f[j] >= th && f[j] > 0.0f) ? f[j] : 0.0f;
        __nv_bfloat16 b1 = __float2bfloat16_rn(h);
        float r = h - __bfloat162float(b1);
        a1[j] = __bfloat16_as_ushort(b1);
        a2[j] = __bfloat16_as_ushort(__float2bfloat16_rn(r));
    }
    reinterpret_cast<ushort4*>(g_H1)[i >> 2] = p1;
    reinterpret_cast<ushort4*>(g_H2)[i >> 2] = p2;
}

__global__ void k_ln(const float* __restrict__ gamma, const float* __restrict__ beta,
                     float* __restrict__ out) {
    __shared__ float ssum[256], ssq[256];
    const int row = blockIdx.x, t = threadIdx.x;
    const float4* xp = reinterpret_cast<const float4*>(g_XO + (size_t)row * DD);
    float4 v0 = xp[t], v1 = xp[t + 256];
    float s = v0.x + v0.y + v0.z + v0.w + v1.x + v1.y + v1.z + v1.w;
    float q = v0.x * v0.x + v0.y * v0.y + v0.z * v0.z + v0.w * v0.w +
              v1.x * v1.x + v1.y * v1.y + v1.z * v1.z + v1.w * v1.w;
    ssum[t] = s; ssq[t] = q; __syncthreads();
    for (int o = 128; o > 0; o >>= 1) {
        if (t < o) { ssum[t] += ssum[t + o]; ssq[t] += ssq[t + o]; }
        __syncthreads();
    }
    float mu  = ssum[0] * (1.0f / DD);
    float var = ssq[0] * (1.0f / DD) - mu * mu;
    float rs  = rsqrtf(var + 1e-5f);
    const float4* gp = reinterpret_cast<const float4*>(gamma);
    const float4* bp = reinterpret_cast<const float4*>(beta);
    float4 g0 = gp[t], g1 = gp[t + 256];
    float4 b0 = bp[t], b1 = bp[t + 256];
    float4 o0, o1;
    o0.x = (v0.x - mu) * rs * g0.x + b0.x; o0.y = (v0.y - mu) * rs * g0.y + b0.y;
    o0.z = (v0.z - mu) * rs * g0.z + b0.z; o0.w = (v0.w - mu) * rs * g0.w + b0.w;
    o1.x = (v1.x - mu) * rs * g1.x + b1.x; o1.y = (v1.y - mu) * rs * g1.y + b1.y;
    o1.z = (v1.z - mu) * rs * g1.z + b1.z; o1.w = (v1.w - mu) * rs * g1.w + b1.w;
    float4* op = reinterpret_cast<float4*>(out + (size_t)row * DD);
    op[t] = o0; op[t + 256] = o1;
}

// ---------------- launcher --------------------------------------------------
extern "C" void kernel_launch(void* const* d_in, const int* in_sizes, int n_in,
                              void* d_out, int out_size) {
    (void)in_sizes; (void)n_in; (void)out_size;
    const float* x     = (const float*)d_in[0];
    const float* W_syn = (const float*)d_in[1];
    const float* b_syn = (const float*)d_in[2];
    const float* W_out = (const float*)d_in[3];
    const float* b_out = (const float*)d_in[4];
    const float* gamma = (const float*)d_in[5];
    const float* beta  = (const float*)d_in[6];
    float* out = (float*)d_out;

    const int SM1 = 3 * 4 * 10240;   // 122880 B
    const int SM2 = 3 * 3 * 10240;   //  92160 B
    cudaFuncSetAttribute(k_gemm_hmma<0, 3>, cudaFuncAttributeMaxDynamicSharedMemorySize, SM1);
    cudaFuncSetAttribute(k_gemm_hmma<1, 2>, cudaFuncAttributeMaxDynamicSharedMemorySize, SM2);

    k_abs_partial<<<2048, 256>>>(W_syn, 0);
    k_abs_partial<<<2048, 256>>>(W_out, 1);
    k_finalize_scales<<<1, 256>>>();
    k_quant<<<16384, 256>>>((const float4*)W_syn, 0);
    k_quant<<<16384, 256>>>((const float4*)W_out, 1);
    k_xlimbs3<<<16384, 256>>>((const float4*)x);
    k_gemm_hmma<0, 3><<<dim3(64, 64), 256, SM1>>>(b_syn, nullptr);
    k_topk<<<MM, 256>>>();
    k_hidden<<<65536, 256>>>();
    k_gemm_hmma<1, 2><<<dim3(16, 64), 256, SM2>>>(b_out, x);
    k_ln<<<MM, 256>>>(gamma, beta, out);
}

// round 8
// speedup vs baseline: 2.4407x; 1.0902x over previous
#include <cuda_runtime.h>
#include <cuda_bf16.h>
#include <cstdint>

#define MM 8192
#define DD 2048
#define NN 8192
#define TOPK 819
typedef unsigned short u16;

__device__ double g_partial[4096];
__device__ float  g_scale[2];
__device__ __align__(16) u16   g_X1[(size_t)MM * DD];
__device__ __align__(16) u16   g_X2[(size_t)MM * DD];
__device__ __align__(16) u16   g_X3[(size_t)MM * DD];
__device__ __align__(16) u16   g_Q1[(size_t)NN * DD];
__device__ __align__(16) u16   g_Q2[(size_t)DD * NN];
__device__ __align__(16) float g_Z [(size_t)MM * NN];
__device__ __align__(16) u16   g_H1[(size_t)MM * NN];
__device__ __align__(16) u16   g_H2[(size_t)MM * NN];
__device__ __align__(16) float g_XO[(size_t)MM * DD];

__device__ __forceinline__ uint32_t smem_u32(const void* p) {
    uint32_t a;
    asm("{ .reg .u64 t; cvta.to.shared.u64 t, %1; cvt.u32.u64 %0, t; }" : "=r"(a) : "l"(p));
    return a;
}
#define CP_COMMIT() asm volatile("cp.async.commit_group;" ::: "memory")
#define CP_WAIT(n)  asm volatile("cp.async.wait_group %0;" :: "n"(n) : "memory")

__device__ __forceinline__ void ldsm4(uint32_t* r, uint32_t addr) {
    asm volatile("ldmatrix.sync.aligned.m8n8.x4.shared.b16 {%0,%1,%2,%3}, [%4];"
                 : "=r"(r[0]), "=r"(r[1]), "=r"(r[2]), "=r"(r[3]) : "r"(addr));
}
__device__ __forceinline__ void mma16816(float* c, uint32_t a0, uint32_t a1,
                                         uint32_t a2, uint32_t a3,
                                         uint32_t b0, uint32_t b1) {
    asm volatile(
        "mma.sync.aligned.m16n8k16.row.col.f32.bf16.bf16.f32 "
        "{%0,%1,%2,%3}, {%4,%5,%6,%7}, {%8,%9}, {%0,%1,%2,%3};\n"
        : "+f"(c[0]), "+f"(c[1]), "+f"(c[2]), "+f"(c[3])
        : "r"(a0), "r"(a1), "r"(a2), "r"(a3), "r"(b0), "r"(b1));
}

// ---------------- prep ------------------------------------------------------
__global__ void k_abs_partial(const float* __restrict__ W, int which) {
    __shared__ double sd[256];
    size_t base = (size_t)blockIdx.x * 8192 + threadIdx.x;
    double s = 0.0;
#pragma unroll
    for (int i = 0; i < 32; i++) s += (double)fabsf(W[base + (size_t)i * 256]);
    sd[threadIdx.x] = s; __syncthreads();
    for (int o = 128; o > 0; o >>= 1) {
        if ((int)threadIdx.x < o) sd[threadIdx.x] += sd[threadIdx.x + o];
        __syncthreads();
    }
    if (threadIdx.x == 0) g_partial[which * 2048 + blockIdx.x] = sd[0];
}
__global__ void k_finalize_scales() {
    __shared__ double sd[256];
    for (int w = 0; w < 2; w++) {
        double s = 0.0;
        for (int i = threadIdx.x; i < 2048; i += 256) s += g_partial[w * 2048 + i];
        sd[threadIdx.x] = s; __syncthreads();
        for (int o = 128; o > 0; o >>= 1) {
            if ((int)threadIdx.x < o) sd[threadIdx.x] += sd[threadIdx.x + o];
            __syncthreads();
        }
        if (threadIdx.x == 0) g_scale[w] = (float)(sd[0] / 16777216.0);
        __syncthreads();
    }
}
__device__ __forceinline__ u16 tq1(float w, float den) {
    float t = __fdiv_rn(w, den);
    float q = fmaxf(-1.0f, fminf(1.0f, rintf(t)));
    return __bfloat16_as_ushort(__float2bfloat16_rn(q));
}
__global__ void k_quant(const float4* __restrict__ W, int which) {
    size_t i = (size_t)blockIdx.x * blockDim.x + threadIdx.x;
    float den = g_scale[which] + 1e-8f;
    float4 w = W[i];
    ushort4 q;
    q.x = tq1(w.x, den); q.y = tq1(w.y, den); q.z = tq1(w.z, den); q.w = tq1(w.w, den);
    reinterpret_cast<ushort4*>(which ? g_Q2 : g_Q1)[i] = q;
}
__global__ void k_xlimbs3(const float4* __restrict__ x) {
    size_t i = (size_t)blockIdx.x * blockDim.x + threadIdx.x;
    float4 v = x[i];
    float f[4] = {v.x, v.y, v.z, v.w};
    ushort4 p1, p2, p3;
    u16* a1 = &p1.x; u16* a2 = &p2.x; u16* a3 = &p3.x;
#pragma unroll
    for (int j = 0; j < 4; j++) {
        __nv_bfloat16 b1 = __float2bfloat16_rn(f[j]);
        float r1 = f[j] - __bfloat162float(b1);
        __nv_bfloat16 b2 = __float2bfloat16_rn(r1);
        float r2 = r1 - __bfloat162float(b2);
        a1[j] = __bfloat16_as_ushort(b1);
        a2[j] = __bfloat16_as_ushort(b2);
        a3[j] = __bfloat16_as_ushort(__float2bfloat16_rn(r2));
    }
    reinterpret_cast<ushort4*>(g_X1)[i] = p1;
    reinterpret_cast<ushort4*>(g_X2)[i] = p2;
    reinterpret_cast<ushort4*>(g_X3)[i] = p3;
}

// ---------------- pipelined HMMA GEMM, ldmatrix fragments -------------------
// CTA 128(m) x 256(n), 8 warps (2m x 4n), warp tile 64x64, k-step 32,
// 3-stage cp.async. smem rows padded to 80B -> conflict-free ldmatrix phases.
template<int GID, int NLIMB>
__global__ void __launch_bounds__(256) k_gemm_hmma(
    const float* __restrict__ bias, const float* __restrict__ xres) {
    constexpr int AT = 10240;                 // 128 rows * 80B
    constexpr int BT = 20480;                 // 256 rows * 80B
    constexpr int STAGE = NLIMB * AT + BT;
    constexpr int Kdim = (GID == 0) ? DD : NN;
    constexpr int Nout = (GID == 0) ? NN : DD;
    constexpr int steps = Kdim >> 5;

    extern __shared__ char sm[];
    const uint32_t smaddr = smem_u32(sm);
    const int tid = threadIdx.x;
    const int warp = tid >> 5, lane = tid & 31;
    const int wm = warp >> 2, wn = warp & 3;
    const int tr = lane >> 2, tc = lane & 3;
    const int m0 = blockIdx.y * 128, n0 = blockIdx.x * 256;

    const u16* At[3];
    if (GID == 0) { At[0] = g_X1; At[1] = g_X2; At[2] = g_X3; }
    else          { At[0] = g_H1; At[1] = g_H2; At[2] = g_H2; }
    const u16* Bq = (GID == 0) ? g_Q1 : g_Q2;
    float* Cout = (GID == 0) ? g_Z : g_XO;

    float acc[4][8][4];
#pragma unroll
    for (int a = 0; a < 4; a++)
#pragma unroll
        for (int b = 0; b < 8; b++)
#pragma unroll
            for (int c = 0; c < 4; c++) acc[a][b][c] = 0.0f;

    const int lrow = tid >> 2, lcol = (tid & 3) * 16;
    // ldmatrix per-lane offsets (bytes within a tile)
    const uint32_t aoff = (uint32_t)((wm * 64 + (lane & 15)) * 80 + ((lane & 16) ? 16 : 0));
    const uint32_t boff = (uint32_t)((wn * 64 + (lane & 7) + ((lane & 16) ? 8 : 0)) * 80 +
                                     ((lane & 8) ? 16 : 0));

    // prologue: stages 0,1
#pragma unroll
    for (int st = 0; st < 2; st++) {
        const int kk = st * 32;
#pragma unroll
        for (int l = 0; l < NLIMB; l++) {
#pragma unroll
            for (int c = 0; c < 2; c++) {
                int row = lrow + c * 64;
                uint32_t dst = smaddr + st * STAGE + l * AT + row * 80 + lcol;
                const char* src = (const char*)(At[l] + (size_t)(m0 + row) * Kdim + kk) + lcol;
                asm volatile("cp.async.cg.shared.global [%0], [%1], 16;" :: "r"(dst), "l"(src) : "memory");
            }
        }
#pragma unroll
        for (int c = 0; c < 4; c++) {
            int row = lrow + c * 64;
            uint32_t dst = smaddr + st * STAGE + NLIMB * AT + row * 80 + lcol;
            const char* src = (const char*)(Bq + (size_t)(n0 + row) * Kdim + kk) + lcol;
            asm volatile("cp.async.cg.shared.global [%0], [%1], 16;" :: "r"(dst), "l"(src) : "memory");
        }
        CP_COMMIT();
    }

    for (int t = 0; t < steps; t++) {
        CP_WAIT(1);
        __syncthreads();
        if (t + 2 < steps) {
            const int st = (t + 2) % 3, kk = (t + 2) * 32;
#pragma unroll
            for (int l = 0; l < NLIMB; l++) {
#pragma unroll
                for (int c = 0; c < 2; c++) {
                    int row = lrow + c * 64;
                    uint32_t dst = smaddr + st * STAGE + l * AT + row * 80 + lcol;
                    const char* src = (const char*)(At[l] + (size_t)(m0 + row) * Kdim + kk) + lcol;
                    asm volatile("cp.async.cg.shared.global [%0], [%1], 16;" :: "r"(dst), "l"(src) : "memory");
                }
            }
#pragma unroll
            for (int c = 0; c < 4; c++) {
                int row = lrow + c * 64;
                uint32_t dst = smaddr + st * STAGE + NLIMB * AT + row * 80 + lcol;
                const char* src = (const char*)(Bq + (size_t)(n0 + row) * Kdim + kk) + lcol;
                asm volatile("cp.async.cg.shared.global [%0], [%1], 16;" :: "r"(dst), "l"(src) : "memory");
            }
        }
        CP_COMMIT();

        const uint32_t sstage = smaddr + (t % 3) * STAGE;
        const uint32_t sB = sstage + NLIMB * AT;
#pragma unroll
        for (int h = 0; h < 2; h++) {
            uint32_t breg[4][4];
#pragma unroll
            for (int nb = 0; nb < 4; nb++)
                ldsm4(breg[nb], sB + boff + nb * 1280 + h * 32);
#pragma unroll
            for (int l = 0; l < NLIMB; l++) {
                uint32_t areg[4][4];
#pragma unroll
                for (int mt = 0; mt < 4; mt++)
                    ldsm4(areg[mt], sstage + l * AT + aoff + mt * 1280 + h * 32);
#pragma unroll
                for (int mt = 0; mt < 4; mt++)
#pragma unroll
                    for (int nt = 0; nt < 8; nt++)
                        mma16816(acc[mt][nt], areg[mt][0], areg[mt][1], areg[mt][2], areg[mt][3],
                                 breg[nt >> 1][(nt & 1) * 2], breg[nt >> 1][(nt & 1) * 2 + 1]);
            }
        }
    }

    const float sc = g_scale[GID];
#pragma unroll
    for (int mt = 0; mt < 4; mt++) {
        int r = m0 + wm * 64 + mt * 16 + tr;
#pragma unroll
        for (int nt = 0; nt < 8; nt++) {
            int n = n0 + wn * 64 + nt * 8 + tc * 2;
            float2 bs = *reinterpret_cast<const float2*>(bias + n);
            float2 o0 = make_float2(fmaf(acc[mt][nt][0], sc, bs.x),
                                    fmaf(acc[mt][nt][1], sc, bs.y));
            float2 o1 = make_float2(fmaf(acc[mt][nt][2], sc, bs.x),
                                    fmaf(acc[mt][nt][3], sc, bs.y));
            if (GID == 1) {
                float2 x0 = *reinterpret_cast<const float2*>(xres + (size_t)r * Nout + n);
                float2 x1 = *reinterpret_cast<const float2*>(xres + (size_t)(r + 8) * Nout + n);
                o0.x += x0.x; o0.y += x0.y; o1.x += x1.x; o1.y += x1.y;
            }
            *reinterpret_cast<float2*>(Cout + (size_t)r * Nout + n)       = o0;
            *reinterpret_cast<float2*>(Cout + (size_t)(r + 8) * Nout + n) = o1;
        }
    }
}

// ---------------- exact per-row kth-largest + fused hidden-limb write ------
__device__ __forceinline__ uint32_t fmap(float f) {
    uint32_t b = __float_as_uint(f);
    return (b & 0x80000000u) ? ~b : (b | 0x80000000u);
}
__device__ __forceinline__ float funmap(uint32_t u) {
    uint32_t bits = (u & 0x80000000u) ? (u ^ 0x80000000u) : ~u;
    return __uint_as_float(bits);
}
__global__ void k_topk_hidden() {
    __shared__ uint32_t srow[NN];
    __shared__ uint32_t hist[256];
    __shared__ uint32_t s_prefix, s_kk;
    const int row = blockIdx.x;
    const uint4* zp = reinterpret_cast<const uint4*>(g_Z + (size_t)row * NN);
    for (int i = threadIdx.x; i < NN / 4; i += 256) {
        uint4 v = zp[i];
        srow[i * 4 + 0] = fmap(__uint_as_float(v.x));
        srow[i * 4 + 1] = fmap(__uint_as_float(v.y));
        srow[i * 4 + 2] = fmap(__uint_as_float(v.z));
        srow[i * 4 + 3] = fmap(__uint_as_float(v.w));
    }
    if (threadIdx.x == 0) { s_prefix = 0u; s_kk = TOPK; }
    __syncthreads();
    uint32_t maskhi = 0u;
    for (int b = 3; b >= 0; b--) {
        hist[threadIdx.x] = 0u;
        __syncthreads();
        const uint32_t pref = s_prefix;
        const int sh = 8 * b;
        for (int i = threadIdx.x; i < NN; i += 256) {
            uint32_t u = srow[i];
            if ((u & maskhi) == pref) atomicAdd(&hist[(u >> sh) & 0xFF], 1u);
        }
        __syncthreads();
        if (threadIdx.x == 0) {
            uint32_t cum = 0, kk = s_kk; int sel = 0;
            for (int v = 255; v >= 0; v--) {
                uint32_t c = hist[v];
                if (cum + c >= kk) { sel = v; s_kk = kk - cum; break; }
                cum += c;
            }
            s_prefix = pref | ((uint32_t)sel << sh);
        }
        __syncthreads();
        maskhi |= (0xFFu << (8 * b));
    }
    const float th = funmap(s_prefix);
    // fused: hidden = where(z>=th, relu(z), 0) -> 2 bf16 limb planes
    for (int i = threadIdx.x; i < NN / 4; i += 256) {
        ushort4 p1, p2;
        u16* a1 = &p1.x; u16* a2 = &p2.x;
#pragma unroll
        for (int j = 0; j < 4; j++) {
            float z = funmap(srow[i * 4 + j]);
            float h = (z >= th && z > 0.0f) ? z : 0.0f;
            __nv_bfloat16 b1 = __float2bfloat16_rn(h);
            float r = h - __bfloat162float(b1);
            a1[j] = __bfloat16_as_ushort(b1);
            a2[j] = __bfloat16_as_ushort(__float2bfloat16_rn(r));
        }
        reinterpret_cast<ushort4*>(g_H1 + (size_t)row * NN)[i] = p1;
        reinterpret_cast<ushort4*>(g_H2 + (size_t)row * NN)[i] = p2;
    }
}

__global__ void k_ln(const float* __restrict__ gamma, const float* __restrict__ beta,
                     float* __restrict__ out) {
    __shared__ float ssum[256], ssq[256];
    const int row = blockIdx.x, t = threadIdx.x;
    const float4* xp = reinterpret_cast<const float4*>(g_XO + (size_t)row * DD);
    float4 v0 = xp[t], v1 = xp[t + 256];
    float s = v0.x + v0.y + v0.z + v0.w + v1.x + v1.y + v1.z + v1.w;
    float q = v0.x * v0.x + v0.y * v0.y + v0.z * v0.z + v0.w * v0.w +
              v1.x * v1.x + v1.y * v1.y + v1.z * v1.z + v1.w * v1.w;
    ssum[t] = s; ssq[t] = q; __syncthreads();
    for (int o = 128; o > 0; o >>= 1) {
        if (t < o) { ssum[t] += ssum[t + o]; ssq[t] += ssq[t + o]; }
        __syncthreads();
    }
    float mu  = ssum[0] * (1.0f / DD);
    float var = ssq[0] * (1.0f / DD) - mu * mu;
    float rs  = rsqrtf(var + 1e-5f);
    const float4* gp = reinterpret_cast<const float4*>(gamma);
    const float4* bp = reinterpret_cast<const float4*>(beta);
    float4 g0 = gp[t], g1 = gp[t + 256];
    float4 b0 = bp[t], b1 = bp[t + 256];
    float4 o0, o1;
    o0.x = (v0.x - mu) * rs * g0.x + b0.x; o0.y = (v0.y - mu) * rs * g0.y + b0.y;
    o0.z = (v0.z - mu) * rs * g0.z + b0.z; o0.w = (v0.w - mu) * rs * g0.w + b0.w;
    o1.x = (v1.x - mu) * rs * g1.x + b1.x; o1.y = (v1.y - mu) * rs * g1.y + b1.y;
    o1.z = (v1.z - mu) * rs * g1.z + b1.z; o1.w = (v1.w - mu) * rs * g1.w + b1.w;
    float4* op = reinterpret_cast<float4*>(out + (size_t)row * DD);
    op[t] = o0; op[t + 256] = o1;
}

// ---------------- launcher --------------------------------------------------
extern "C" void kernel_launch(void* const* d_in, const int* in_sizes, int n_in,
                              void* d_out, int out_size) {
    (void)in_sizes; (void)n_in; (void)out_size;
    const float* x     = (const float*)d_in[0];
    const float* W_syn = (const float*)d_in[1];
    const float* b_syn = (const float*)d_in[2];
    const float* W_out = (const float*)d_in[3];
    const float* b_out = (const float*)d_in[4];
    const float* gamma = (const float*)d_in[5];
    const float* beta  = (const float*)d_in[6];
    float* out = (float*)d_out;

    const int SM1 = 3 * (3 * 10240 + 20480);   // 153600 B
    const int SM2 = 3 * (2 * 10240 + 20480);   // 122880 B
    cudaFuncSetAttribute(k_gemm_hmma<0, 3>, cudaFuncAttributeMaxDynamicSharedMemorySize, SM1);
    cudaFuncSetAttribute(k_gemm_hmma<1, 2>, cudaFuncAttributeMaxDynamicSharedMemorySize, SM2);

    k_abs_partial<<<2048, 256>>>(W_syn, 0);
    k_abs_partial<<<2048, 256>>>(W_out, 1);
    k_finalize_scales<<<1, 256>>>();
    k_quant<<<16384, 256>>>((const float4*)W_syn, 0);
    k_quant<<<16384, 256>>>((const float4*)W_out, 1);
    k_xlimbs3<<<16384, 256>>>((const float4*)x);
    k_gemm_hmma<0, 3><<<dim3(32, 64), 256, SM1>>>(b_syn, nullptr);
    k_topk_hidden<<<MM, 256>>>();
    k_gemm_hmma<1, 2><<<dim3(8, 64), 256, SM2>>>(b_out, x);
    k_ln<<<MM, 256>>>(gamma, beta, out);
}

// round 9
// speedup vs baseline: 2.5078x; 1.0275x over previous
#include <cuda_runtime.h>
#include <cuda_bf16.h>
#include <cstdint>

#define MM 8192
#define DD 2048
#define NN 8192
#define TOPK 819
#define BANDCAP 192
typedef unsigned short u16;

__device__ double g_partial[4096];
__device__ float  g_scale[2];
__device__ __align__(16) u16   g_X1[(size_t)MM * DD];
__device__ __align__(16) u16   g_X2[(size_t)MM * DD];
__device__ __align__(16) u16   g_Q1[(size_t)NN * DD];
__device__ __align__(16) u16   g_Q2[(size_t)DD * NN];
__device__ __align__(16) float g_Z [(size_t)MM * NN];
__device__ __align__(16) u16   g_H1[(size_t)MM * NN];
__device__ __align__(16) float g_XO[(size_t)MM * DD];

__device__ __forceinline__ uint32_t smem_u32(const void* p) {
    uint32_t a;
    asm("{ .reg .u64 t; cvta.to.shared.u64 t, %1; cvt.u32.u64 %0, t; }" : "=r"(a) : "l"(p));
    return a;
}
#define CP_COMMIT() asm volatile("cp.async.commit_group;" ::: "memory")
#define CP_WAIT(n)  asm volatile("cp.async.wait_group %0;" :: "n"(n) : "memory")

__device__ __forceinline__ void ldsm4(uint32_t* r, uint32_t addr) {
    asm volatile("ldmatrix.sync.aligned.m8n8.x4.shared.b16 {%0,%1,%2,%3}, [%4];"
                 : "=r"(r[0]), "=r"(r[1]), "=r"(r[2]), "=r"(r[3]) : "r"(addr));
}
__device__ __forceinline__ void mma16816(float* c, uint32_t a0, uint32_t a1,
                                         uint32_t a2, uint32_t a3,
                                         uint32_t b0, uint32_t b1) {
    asm volatile(
        "mma.sync.aligned.m16n8k16.row.col.f32.bf16.bf16.f32 "
        "{%0,%1,%2,%3}, {%4,%5,%6,%7}, {%8,%9}, {%0,%1,%2,%3};\n"
        : "+f"(c[0]), "+f"(c[1]), "+f"(c[2]), "+f"(c[3])
        : "r"(a0), "r"(a1), "r"(a2), "r"(a3), "r"(b0), "r"(b1));
}

// ---------------- prep ------------------------------------------------------
__global__ void k_abs_partial(const float* __restrict__ W, int which) {
    __shared__ double sd[256];
    size_t base = (size_t)blockIdx.x * 8192 + threadIdx.x;
    double s = 0.0;
#pragma unroll
    for (int i = 0; i < 32; i++) s += (double)fabsf(W[base + (size_t)i * 256]);
    sd[threadIdx.x] = s; __syncthreads();
    for (int o = 128; o > 0; o >>= 1) {
        if ((int)threadIdx.x < o) sd[threadIdx.x] += sd[threadIdx.x + o];
        __syncthreads();
    }
    if (threadIdx.x == 0) g_partial[which * 2048 + blockIdx.x] = sd[0];
}
__global__ void k_finalize_scales() {
    __shared__ double sd[256];
    for (int w = 0; w < 2; w++) {
        double s = 0.0;
        for (int i = threadIdx.x; i < 2048; i += 256) s += g_partial[w * 2048 + i];
        sd[threadIdx.x] = s; __syncthreads();
        for (int o = 128; o > 0; o >>= 1) {
            if ((int)threadIdx.x < o) sd[threadIdx.x] += sd[threadIdx.x + o];
            __syncthreads();
        }
        if (threadIdx.x == 0) g_scale[w] = (float)(sd[0] / 16777216.0);
        __syncthreads();
    }
}
__device__ __forceinline__ u16 tq1(float w, float den) {
    float t = __fdiv_rn(w, den);
    float q = fmaxf(-1.0f, fminf(1.0f, rintf(t)));
    return __bfloat16_as_ushort(__float2bfloat16_rn(q));
}
__global__ void k_quant(const float4* __restrict__ W, int which) {
    size_t i = (size_t)blockIdx.x * blockDim.x + threadIdx.x;
    float den = g_scale[which] + 1e-8f;
    float4 w = W[i];
    ushort4 q;
    q.x = tq1(w.x, den); q.y = tq1(w.y, den); q.z = tq1(w.z, den); q.w = tq1(w.w, den);
    reinterpret_cast<ushort4*>(which ? g_Q2 : g_Q1)[i] = q;
}
__global__ void k_xlimbs2(const float4* __restrict__ x) {
    size_t i = (size_t)blockIdx.x * blockDim.x + threadIdx.x;
    float4 v = x[i];
    float f[4] = {v.x, v.y, v.z, v.w};
    ushort4 p1, p2;
    u16* a1 = &p1.x; u16* a2 = &p2.x;
#pragma unroll
    for (int j = 0; j < 4; j++) {
        __nv_bfloat16 b1 = __float2bfloat16_rn(f[j]);
        float r1 = f[j] - __bfloat162float(b1);
        a1[j] = __bfloat16_as_ushort(b1);
        a2[j] = __bfloat16_as_ushort(__float2bfloat16_rn(r1));
    }
    reinterpret_cast<ushort4*>(g_X1)[i] = p1;
    reinterpret_cast<ushort4*>(g_X2)[i] = p2;
}

// ---------------- pipelined HMMA GEMM, ldmatrix fragments -------------------
// CTA 128(m) x 256(n), 8 warps (2m x 4n), warp tile 64x64, k-step 32,
// 3-stage cp.async. smem rows padded to 80B -> conflict-free ldmatrix phases.
template<int GID, int NLIMB>
__global__ void __launch_bounds__(256) k_gemm_hmma(
    const float* __restrict__ bias, const float* __restrict__ xres) {
    constexpr int AT = 10240;                 // 128 rows * 80B
    constexpr int BT = 20480;                 // 256 rows * 80B
    constexpr int STAGE = NLIMB * AT + BT;
    constexpr int Kdim = (GID == 0) ? DD : NN;
    constexpr int Nout = (GID == 0) ? NN : DD;
    constexpr int steps = Kdim >> 5;

    extern __shared__ char sm[];
    const uint32_t smaddr = smem_u32(sm);
    const int tid = threadIdx.x;
    const int warp = tid >> 5, lane = tid & 31;
    const int wm = warp >> 2, wn = warp & 3;
    const int tr = lane >> 2, tc = lane & 3;
    const int m0 = blockIdx.y * 128, n0 = blockIdx.x * 256;

    const u16* At[2];
    if (GID == 0) { At[0] = g_X1; At[1] = g_X2; }
    else          { At[0] = g_H1; At[1] = g_H1; }
    const u16* Bq = (GID == 0) ? g_Q1 : g_Q2;
    float* Cout = (GID == 0) ? g_Z : g_XO;

    float acc[4][8][4];
#pragma unroll
    for (int a = 0; a < 4; a++)
#pragma unroll
        for (int b = 0; b < 8; b++)
#pragma unroll
            for (int c = 0; c < 4; c++) acc[a][b][c] = 0.0f;

    const int lrow = tid >> 2, lcol = (tid & 3) * 16;
    const uint32_t aoff = (uint32_t)((wm * 64 + (lane & 15)) * 80 + ((lane & 16) ? 16 : 0));
    const uint32_t boff = (uint32_t)((wn * 64 + (lane & 7) + ((lane & 16) ? 8 : 0)) * 80 +
                                     ((lane & 8) ? 16 : 0));

#pragma unroll
    for (int st = 0; st < 2; st++) {
        const int kk = st * 32;
#pragma unroll
        for (int l = 0; l < NLIMB; l++) {
#pragma unroll
            for (int c = 0; c < 2; c++) {
                int row = lrow + c * 64;
                uint32_t dst = smaddr + st * STAGE + l * AT + row * 80 + lcol;
                const char* src = (const char*)(At[l] + (size_t)(m0 + row) * Kdim + kk) + lcol;
                asm volatile("cp.async.cg.shared.global [%0], [%1], 16;" :: "r"(dst), "l"(src) : "memory");
            }
        }
#pragma unroll
        for (int c = 0; c < 4; c++) {
            int row = lrow + c * 64;
            uint32_t dst = smaddr + st * STAGE + NLIMB * AT + row * 80 + lcol;
            const char* src = (const char*)(Bq + (size_t)(n0 + row) * Kdim + kk) + lcol;
            asm volatile("cp.async.cg.shared.global [%0], [%1], 16;" :: "r"(dst), "l"(src) : "memory");
        }
        CP_COMMIT();
    }

    for (int t = 0; t < steps; t++) {
        CP_WAIT(1);
        __syncthreads();
        if (t + 2 < steps) {
            const int st = (t + 2) % 3, kk = (t + 2) * 32;
#pragma unroll
            for (int l = 0; l < NLIMB; l++) {
#pragma unroll
                for (int c = 0; c < 2; c++) {
                    int row = lrow + c * 64;
                    uint32_t dst = smaddr + st * STAGE + l * AT + row * 80 + lcol;
                    const char* src = (const char*)(At[l] + (size_t)(m0 + row) * Kdim + kk) + lcol;
                    asm volatile("cp.async.cg.shared.global [%0], [%1], 16;" :: "r"(dst), "l"(src) : "memory");
                }
            }
#pragma unroll
            for (int c = 0; c < 4; c++) {
                int row = lrow + c * 64;
                uint32_t dst = smaddr + st * STAGE + NLIMB * AT + row * 80 + lcol;
                const char* src = (const char*)(Bq + (size_t)(n0 + row) * Kdim + kk) + lcol;
                asm volatile("cp.async.cg.shared.global [%0], [%1], 16;" :: "r"(dst), "l"(src) : "memory");
            }
        }
        CP_COMMIT();

        const uint32_t sstage = smaddr + (t % 3) * STAGE;
        const uint32_t sB = sstage + NLIMB * AT;
#pragma unroll
        for (int h = 0; h < 2; h++) {
            uint32_t breg[4][4];
#pragma unroll
            for (int nb = 0; nb < 4; nb++)
                ldsm4(breg[nb], sB + boff + nb * 1280 + h * 32);
#pragma unroll
            for (int l = 0; l < NLIMB; l++) {
                uint32_t areg[4][4];
#pragma unroll
                for (int mt = 0; mt < 4; mt++)
                    ldsm4(areg[mt], sstage + l * AT + aoff + mt * 1280 + h * 32);
#pragma unroll
                for (int mt = 0; mt < 4; mt++)
#pragma unroll
                    for (int nt = 0; nt < 8; nt++)
                        mma16816(acc[mt][nt], areg[mt][0], areg[mt][1], areg[mt][2], areg[mt][3],
                                 breg[nt >> 1][(nt & 1) * 2], breg[nt >> 1][(nt & 1) * 2 + 1]);
            }
        }
    }

    const float sc = g_scale[GID];
#pragma unroll
    for (int mt = 0; mt < 4; mt++) {
        int r = m0 + wm * 64 + mt * 16 + tr;
#pragma unroll
        for (int nt = 0; nt < 8; nt++) {
            int n = n0 + wn * 64 + nt * 8 + tc * 2;
            float2 bs = *reinterpret_cast<const float2*>(bias + n);
            float2 o0 = make_float2(fmaf(acc[mt][nt][0], sc, bs.x),
                                    fmaf(acc[mt][nt][1], sc, bs.y));
            float2 o1 = make_float2(fmaf(acc[mt][nt][2], sc, bs.x),
                                    fmaf(acc[mt][nt][3], sc, bs.y));
            if (GID == 1) {
                float2 x0 = *reinterpret_cast<const float2*>(xres + (size_t)r * Nout + n);
                float2 x1 = *reinterpret_cast<const float2*>(xres + (size_t)(r + 8) * Nout + n);
                o0.x += x0.x; o0.y += x0.y; o1.x += x1.x; o1.y += x1.y;
            }
            *reinterpret_cast<float2*>(Cout + (size_t)r * Nout + n)       = o0;
            *reinterpret_cast<float2*>(Cout + (size_t)(r + 8) * Nout + n) = o1;
        }
    }
}

// ------- top-k with banded exact repair + fused hidden (1 limb) -----------
__device__ __forceinline__ uint32_t fmap(float f) {
    uint32_t b = __float_as_uint(f);
    return (b & 0x80000000u) ? ~b : (b | 0x80000000u);
}
__device__ __forceinline__ float funmap(uint32_t u) {
    uint32_t bits = (u & 0x80000000u) ? (u ^ 0x80000000u) : ~u;
    return __uint_as_float(bits);
}
__global__ void k_topk_repair(const float* __restrict__ x,
                              const float* __restrict__ b_syn) {
    __shared__ uint32_t srow[NN];          // 32KB: z2 (sortable-mapped)
    __shared__ float    xs[DD];            // 8KB: x row fp32
    __shared__ uint32_t hist[256];
    __shared__ double   bz[BANDCAP];
    __shared__ int      bidx[BANDCAP];
    __shared__ unsigned char binc[BANDCAP];
    __shared__ uint32_t s_prefix, s_kk;
    __shared__ int      s_A, s_cnt;
    const int row = blockIdx.x, tid = threadIdx.x;
    const int warp = tid >> 5, lane = tid & 31;

    const uint4* zp = reinterpret_cast<const uint4*>(g_Z + (size_t)row * NN);
    for (int i = tid; i < NN / 4; i += 256) {
        uint4 v = zp[i];
        srow[i * 4 + 0] = fmap(__uint_as_float(v.x));
        srow[i * 4 + 1] = fmap(__uint_as_float(v.y));
        srow[i * 4 + 2] = fmap(__uint_as_float(v.z));
        srow[i * 4 + 3] = fmap(__uint_as_float(v.w));
    }
    for (int i = tid; i < DD; i += 256) xs[i] = x[(size_t)row * DD + i];
    if (tid == 0) { s_prefix = 0u; s_kk = TOPK; s_A = 0; s_cnt = 0; }
    __syncthreads();

    // exact radix select: th2 = kth largest of z2
    uint32_t maskhi = 0u;
    for (int b = 3; b >= 0; b--) {
        hist[tid] = 0u;
        __syncthreads();
        const uint32_t pref = s_prefix;
        const int sh = 8 * b;
        for (int i = tid; i < NN; i += 256) {
            uint32_t u = srow[i];
            if ((u & maskhi) == pref) atomicAdd(&hist[(u >> sh) & 0xFF], 1u);
        }
        __syncthreads();
        if (tid == 0) {
            uint32_t cum = 0, kk = s_kk; int sel = 0;
            for (int v = 255; v >= 0; v--) {
                uint32_t c = hist[v];
                if (cum + c >= kk) { sel = v; s_kk = kk - cum; break; }
                cum += c;
            }
            s_prefix = pref | ((uint32_t)sel << sh);
        }
        __syncthreads();
        maskhi |= (0xFFu << (8 * b));
    }
    const float th2 = funmap(s_prefix);
    const float thhi = th2 + 3e-3f;
    const float thlo = th2 - 3e-3f;

    // pass 1: count definite-ins, gather band
    for (int i = tid; i < NN; i += 256) {
        float z = funmap(srow[i]);
        if (z > thhi) atomicAdd(&s_A, 1);
        else if (z >= thlo) {
            int p = atomicAdd(&s_cnt, 1);
            if (p < BANDCAP) bidx[p] = i;
        }
    }
    __syncthreads();
    const int cnt = min(s_cnt, BANDCAP);
    const int need = TOPK - s_A;

    // exact fp64 dot for each band element (one warp per element)
    const double sc = (double)g_scale[0];
    for (int b = warp; b < cnt; b += 8) {
        const int j = bidx[b];
        const u16* q = g_Q1 + (size_t)j * DD;
        double acc = 0.0;
        for (int k = lane; k < DD; k += 32)
            acc += (double)xs[k] * (double)__bfloat162float(__ushort_as_bfloat16(q[k]));
#pragma unroll
        for (int o = 16; o > 0; o >>= 1) acc += __shfl_down_sync(0xffffffffu, acc, o);
        if (lane == 0) bz[b] = acc * sc + (double)b_syn[j];
    }
    __syncthreads();

    // rank band by exact z: include iff fewer than `need` strictly greater
    for (int b = tid; b < cnt; b += 256) {
        int rank = 0;
        double v = bz[b];
        for (int b2 = 0; b2 < cnt; b2++) rank += (bz[b2] > v);
        binc[b] = (rank < need) ? 1 : 0;
    }
    __syncthreads();

    // hidden (1 bf16 limb): non-band by z2 rule; band fixed after
    u16* hrow = g_H1 + (size_t)row * NN;
    for (int i = tid; i < NN / 4; i += 256) {
        ushort4 p;
        u16* a = &p.x;
#pragma unroll
        for (int j = 0; j < 4; j++) {
            float z = funmap(srow[i * 4 + j]);
            float h = (z > thhi) ? fmaxf(z, 0.0f) : 0.0f;   // band -> 0 (fixed below)
            a[j] = __bfloat16_as_ushort(__float2bfloat16_rn(h));
        }
        reinterpret_cast<ushort4*>(hrow)[i] = p;
    }
    __syncthreads();
    for (int b = tid; b < cnt; b += 256) {
        int j = bidx[b];
        float z = funmap(srow[j]);
        float h = binc[b] ? fmaxf(z, 0.0f) : 0.0f;
        hrow[j] = __bfloat16_as_ushort(__float2bfloat16_rn(h));
    }
}

__global__ void k_ln(const float* __restrict__ gamma, const float* __restrict__ beta,
                     float* __restrict__ out) {
    __shared__ float ssum[256], ssq[256];
    const int row = blockIdx.x, t = threadIdx.x;
    const float4* xp = reinterpret_cast<const float4*>(g_XO + (size_t)row * DD);
    float4 v0 = xp[t], v1 = xp[t + 256];
    float s = v0.x + v0.y + v0.z + v0.w + v1.x + v1.y + v1.z + v1.w;
    float q = v0.x * v0.x + v0.y * v0.y + v0.z * v0.z + v0.w * v0.w +
              v1.x * v1.x + v1.y * v1.y + v1.z * v1.z + v1.w * v1.w;
    ssum[t] = s; ssq[t] = q; __syncthreads();
    for (int o = 128; o > 0; o >>= 1) {
        if (t < o) { ssum[t] += ssum[t + o]; ssq[t] += ssq[t + o]; }
        __syncthreads();
    }
    float mu  = ssum[0] * (1.0f / DD);
    float var = ssq[0] * (1.0f / DD) - mu * mu;
    float rs  = rsqrtf(var + 1e-5f);
    const float4* gp = reinterpret_cast<const float4*>(gamma);
    const float4* bp = reinterpret_cast<const float4*>(beta);
    float4 g0 = gp[t], g1 = gp[t + 256];
    float4 b0 = bp[t], b1 = bp[t + 256];
    float4 o0, o1;
    o0.x = (v0.x - mu) * rs * g0.x + b0.x; o0.y = (v0.y - mu) * rs * g0.y + b0.y;
    o0.z = (v0.z - mu) * rs * g0.z + b0.z; o0.w = (v0.w - mu) * rs * g0.w + b0.w;
    o1.x = (v1.x - mu) * rs * g1.x + b1.x; o1.y = (v1.y - mu) * rs * g1.y + b1.y;
    o1.z = (v1.z - mu) * rs * g1.z + b1.z; o1.w = (v1.w - mu) * rs * g1.w + b1.w;
    float4* op = reinterpret_cast<float4*>(out + (size_t)row * DD);
    op[t] = o0; op[t + 256] = o1;
}

// ---------------- launcher --------------------------------------------------
extern "C" void kernel_launch(void* const* d_in, const int* in_sizes, int n_in,
                              void* d_out, int out_size) {
    (void)in_sizes; (void)n_in; (void)out_size;
    const float* x     = (const float*)d_in[0];
    const float* W_syn = (const float*)d_in[1];
    const float* b_syn = (const float*)d_in[2];
    const float* W_out = (const float*)d_in[3];
    const float* b_out = (const float*)d_in[4];
    const float* gamma = (const float*)d_in[5];
    const float* beta  = (const float*)d_in[6];
    float* out = (float*)d_out;

    const int SM1 = 3 * (2 * 10240 + 20480);   // 122880 B
    const int SM2 = 3 * (1 * 10240 + 20480);   //  92160 B
    cudaFuncSetAttribute(k_gemm_hmma<0, 2>, cudaFuncAttributeMaxDynamicSharedMemorySize, SM1);
    cudaFuncSetAttribute(k_gemm_hmma<1, 1>, cudaFuncAttributeMaxDynamicSharedMemorySize, SM2);

    k_abs_partial<<<2048, 256>>>(W_syn, 0);
    k_abs_partial<<<2048, 256>>>(W_out, 1);
    k_finalize_scales<<<1, 256>>>();
    k_quant<<<16384, 256>>>((const float4*)W_syn, 0);
    k_quant<<<16384, 256>>>((const float4*)W_out, 1);
    k_xlimbs2<<<16384, 256>>>((const float4*)x);
    k_gemm_hmma<0, 2><<<dim3(32, 64), 256, SM1>>>(b_syn, nullptr);
    k_topk_repair<<<MM, 256>>>(x, b_syn);
    k_gemm_hmma<1, 1><<<dim3(8, 64), 256, SM2>>>(b_out, x);
    k_ln<<<MM, 256>>>(gamma, beta, out);
}